// round 12
// baseline (speedup 1.0000x reference)
#include <cuda_runtime.h>
#include <cuda_fp16.h>
#include <math.h>
#include <stdint.h>

// ---------------- static device scratch (no allocation allowed) ----------------
__device__ __half  g_xh  [(size_t)32768 * 2048];   // x converted to fp16
__device__ float   g_xg1 [(size_t)32768 * 1024];   // layer1 gates [b][t][j*4+g] (fp32)
__device__ __half  g_out1[(size_t)32768 * 256];    // layer1 hidden outputs (fp16)
__device__ float   g_xg2 [(size_t)32768 * 512];    // layer2 gates [b][t][j*4+g] (fp32)
__device__ __half  g_w1h [(size_t)1024 * 2048];    // Wih1 fp16
__device__ __half  g_w2h [(size_t)512 * 256];      // Wih2 fp16
__device__ float   g_h2f [64 * 128];               // final layer2 h (fp32)

// ---------------- helpers ----------------
__device__ __forceinline__ void mma_f16(float* c, const unsigned* a, const unsigned* b) {
    asm volatile(
        "mma.sync.aligned.m16n8k16.row.col.f32.f16.f16.f32 "
        "{%0,%1,%2,%3},{%4,%5,%6,%7},{%8,%9},{%0,%1,%2,%3};"
        : "+f"(c[0]), "+f"(c[1]), "+f"(c[2]), "+f"(c[3])
        : "r"(a[0]), "r"(a[1]), "r"(a[2]), "r"(a[3]), "r"(b[0]), "r"(b[1]));
}

__device__ __forceinline__ void ldsm_x4(unsigned& r0, unsigned& r1, unsigned& r2,
                                        unsigned& r3, uint32_t addr) {
    asm volatile("ldmatrix.sync.aligned.m8n8.x4.shared.b16 {%0,%1,%2,%3}, [%4];"
                 : "=r"(r0), "=r"(r1), "=r"(r2), "=r"(r3) : "r"(addr));
}

__device__ __forceinline__ void cp_async16(void* smem_dst, const void* gptr) {
    unsigned s = (unsigned)__cvta_generic_to_shared(smem_dst);
    asm volatile("cp.async.cg.shared.global [%0], [%1], 16;\n" :: "r"(s), "l"(gptr));
}
#define CP_COMMIT() asm volatile("cp.async.commit_group;\n" ::: "memory")
#define CP_WAIT0()  asm volatile("cp.async.wait_group 0;\n" ::: "memory")

__device__ __forceinline__ uint32_t smem_u32(const void* p) {
    return (uint32_t)__cvta_generic_to_shared(p);
}
__device__ __forceinline__ uint32_t my_ctarank() {
    uint32_t r;
    asm("mov.u32 %0, %%cluster_ctarank;" : "=r"(r));
    return r;
}
#define CLUSTER_ARRIVE() asm volatile("barrier.cluster.arrive.aligned;" ::: "memory")
#define CLUSTER_WAIT()   asm volatile("barrier.cluster.wait.aligned;" ::: "memory")

__device__ __forceinline__ void mbar_init(uint32_t a, unsigned cnt) {
    asm volatile("mbarrier.init.shared.b64 [%0], %1;" :: "r"(a), "r"(cnt) : "memory");
}
__device__ __forceinline__ void mbar_expect_tx(uint32_t a, unsigned tx) {
    asm volatile("mbarrier.arrive.expect_tx.shared.b64 _, [%0], %1;"
                 :: "r"(a), "r"(tx) : "memory");
}
__device__ __forceinline__ void mbar_wait(uint32_t a, unsigned parity) {
    asm volatile(
        "{\n\t"
        ".reg .pred P1;\n\t"
        "WAIT_LOOP_%=:\n\t"
        "mbarrier.try_wait.parity.acquire.cta.shared::cta.b64 P1, [%0], %1, 0x989680;\n\t"
        "@P1 bra.uni WAIT_DONE_%=;\n\t"
        "bra.uni WAIT_LOOP_%=;\n\t"
        "WAIT_DONE_%=:\n\t"
        "}"
        :: "r"(a), "r"(parity) : "memory");
}
__device__ __forceinline__ void mbar_arrive_remote(uint32_t local_addr, int rank) {
    uint32_t ra;
    asm("mapa.shared::cluster.u32 %0, %1, %2;" : "=r"(ra) : "r"(local_addr), "r"(rank));
    asm volatile("mbarrier.arrive.shared::cluster.b64 _, [%0];" :: "r"(ra) : "memory");
}
__device__ __forceinline__ void st_async_b32(uint32_t local_dst, unsigned val,
                                             uint32_t local_mbar, int rank) {
    uint32_t ra, rm;
    asm("mapa.shared::cluster.u32 %0, %1, %2;" : "=r"(ra) : "r"(local_dst), "r"(rank));
    asm("mapa.shared::cluster.u32 %0, %1, %2;" : "=r"(rm) : "r"(local_mbar), "r"(rank));
    asm volatile("st.async.shared::cluster.mbarrier::complete_tx::bytes.b32 [%0], %1, [%2];"
                 :: "r"(ra), "r"(val), "r"(rm) : "memory");
}

// fast precise activations
__device__ __forceinline__ float fsigmoid(float x) {
    return 1.f / (1.f + __expf(-x));
}
__device__ __forceinline__ float ftanh(float x) {
    return 1.f - 2.f / (1.f + __expf(2.f * x));
}

// ---------------- prep: convert fp32 -> fp16 ----------------
__global__ void cvt_f16_kernel(const float* __restrict__ src, __half* __restrict__ dst, int n) {
    int i = (blockIdx.x * 256 + threadIdx.x) * 4;
    if (i < n) {
        float4 v = *(const float4*)(src + i);
        *(__half2*)(dst + i)     = __floats2half2_rn(v.x, v.y);
        *(__half2*)(dst + i + 2) = __floats2half2_rn(v.z, v.w);
    }
}

// ---------------- fp16 GEMM (ldmatrix fragments) with permuted output columns ----------------
// C[m][n'] = sum_k A[m][k]*W[srcrow(n')][k] + b1+b2, n'=j*4+g -> g*H+j.
// Tiles: 128M x 128N x 64K, 256 threads (2m x 4n warps, warp tile 64x32),
// double-buffered cp.async, m16n8k16 fp16 mma, LDSM.x4 fragment loads.
__global__ void __launch_bounds__(256, 2) gemm_f16_perm(
    const __half* __restrict__ A, const __half* __restrict__ W,
    const float* __restrict__ b1, const float* __restrict__ b2,
    float* __restrict__ C, int M, int N, int K)
{
    extern __shared__ unsigned sh[];
    unsigned* As = sh;                 // [2][128][36] half2 words (32 used)
    unsigned* Bs = sh + 2 * 128 * 36;  // [2][128][36]

    const int tid = threadIdx.x, lane = tid & 31, warp = tid >> 5;
    const int wm = warp & 1, wn = warp >> 1;
    const int g = lane >> 2, tg = lane & 3;
    const int bn = blockIdx.x * 128, bm = blockIdx.y * 128;
    const int H = N >> 2;

    // per-lane ldmatrix addressing
    const int lrow = lane & 7;
    const int mhi8 = ((lane >> 3) & 1) * 8;
    const int khi4 = (lane >> 4) * 4;
    const uint32_t As_b = smem_u32(As);
    const uint32_t Bs_b = smem_u32(Bs);
    // invariant word offsets (add ks*8 and buf offset later)
    uint32_t aoff[4], boff[2];
#pragma unroll
    for (int mt = 0; mt < 4; mt++)
        aoff[mt] = (uint32_t)(((wm * 64 + mt * 16 + mhi8 + lrow) * 36 + khi4) * 4);
#pragma unroll
    for (int p = 0; p < 2; p++)
        boff[p] = (uint32_t)(((wn * 32 + p * 16 + mhi8 + lrow) * 36 + khi4) * 4);

    float acc[4][4][4];
#pragma unroll
    for (int a = 0; a < 4; a++)
#pragma unroll
        for (int b = 0; b < 4; b++)
#pragma unroll
            for (int c = 0; c < 4; c++) acc[a][b][c] = 0.f;

    const int NK = K >> 6;    // 64 k per tile

    // prologue: tile 0
#pragma unroll
    for (int i = 0; i < 4; i++) {
        int id = tid + i * 256, row = id >> 3, c4 = id & 7;
        cp_async16(&As[row * 36 + c4 * 4], A + (size_t)(bm + row) * K + c4 * 8);
        int np = bn + row;
        int srow = (np & 3) * H + (np >> 2);
        cp_async16(&Bs[row * 36 + c4 * 4], W + (size_t)srow * K + c4 * 8);
    }
    CP_COMMIT();

    int buf = 0;
    for (int kt = 0; kt < NK; kt++) {
        CP_WAIT0();
        __syncthreads();
        if (kt + 1 < NK) {
            int koff = (kt + 1) * 64;
            int nb = buf ^ 1;
#pragma unroll
            for (int i = 0; i < 4; i++) {
                int id = tid + i * 256, row = id >> 3, c4 = id & 7;
                cp_async16(&As[nb * 128 * 36 + row * 36 + c4 * 4],
                           A + (size_t)(bm + row) * K + koff + c4 * 8);
                int np = bn + row;
                int srow = (np & 3) * H + (np >> 2);
                cp_async16(&Bs[nb * 128 * 36 + row * 36 + c4 * 4],
                           W + (size_t)srow * K + koff + c4 * 8);
            }
        }
        CP_COMMIT();

        const uint32_t ab = As_b + (uint32_t)buf * 128 * 36 * 4;
        const uint32_t bb = Bs_b + (uint32_t)buf * 128 * 36 * 4;
#pragma unroll
        for (int ks = 0; ks < 4; ks++) {   // 4 x k=16 slices
            unsigned af[4][4], bf[4][2];
#pragma unroll
            for (int mt = 0; mt < 4; mt++)
                ldsm_x4(af[mt][0], af[mt][1], af[mt][2], af[mt][3],
                        ab + aoff[mt] + (uint32_t)(ks * 32));
#pragma unroll
            for (int p = 0; p < 2; p++) {
                unsigned t0, t1, t2, t3;
                ldsm_x4(t0, t1, t2, t3, bb + boff[p] + (uint32_t)(ks * 32));
                bf[2 * p][0] = t0; bf[2 * p + 1][0] = t1;
                bf[2 * p][1] = t2; bf[2 * p + 1][1] = t3;
            }
#pragma unroll
            for (int mt = 0; mt < 4; mt++)
#pragma unroll
                for (int nt = 0; nt < 4; nt++)
                    mma_f16(acc[mt][nt], af[mt], bf[nt]);
        }
        buf ^= 1;
    }

    // epilogue: permuted bias + fp32 store
#pragma unroll
    for (int mt = 0; mt < 4; mt++) {
        int r0 = bm + wm * 64 + mt * 16 + g;
#pragma unroll
        for (int nt = 0; nt < 4; nt++) {
            int c = bn + wn * 32 + nt * 8 + tg * 2;
            int s0 = (c & 3) * H + (c >> 2);
            int s1 = ((c + 1) & 3) * H + ((c + 1) >> 2);
            float bb0 = b1[s0] + b2[s0];
            float bb1 = b1[s1] + b2[s1];
            C[(size_t)r0 * N + c]           = acc[mt][nt][0] + bb0;
            C[(size_t)r0 * N + c + 1]       = acc[mt][nt][1] + bb1;
            C[(size_t)(r0 + 8) * N + c]     = acc[mt][nt][2] + bb0;
            C[(size_t)(r0 + 8) * N + c + 1] = acc[mt][nt][3] + bb1;
        }
    }
}

// ---------------- cluster LSTM recurrence, warp-local update (no bar.sync in loop) ----------------
// Warp w owns gate rows [w*16, w*16+16) = units {w*4..w*4+3} x 4 gates. Its MMA
// output holds all gates for its 4 units x 8 batches = 32 (u,b) pairs = 32 lanes.
// Gate transpose goes through a per-warp smem patch (syncwarp only); EMPT release
// is per-warp (count NW*8). FULL delivery via st.async tx as before.
template <int HD, int JPC, int NT, bool STORE_OUT>
__global__ void __launch_bounds__(NT, 1) __cluster_dims__(8, 1, 1)
lstm_recur_w(const float* __restrict__ xg,    // [b][t][j*4+g] fp32
             const float* __restrict__ Whh,   // [4*HD][HD] fp32
             __half* __restrict__ out,        // [b][t][HD] fp16 (layer1) or null
             float* __restrict__ hfin,        // [64][HD] fp32 (layer2) or null
             int T)
{
    constexpr int KS = HD / 16;            // mma k-steps
    constexpr int HW = HD / 2 + 4;         // padded half2-words per batch row
    constexpr int NW = NT / 32;            // warps
    constexpr unsigned FBYTES = 16u * HD;  // 8 batches * HD * 2 B per phase
    constexpr unsigned ECNT = (unsigned)(NW * 8);

    extern __shared__ unsigned smem_u[];
    unsigned* hs = smem_u + 8;                   // [2][8][HW] half2 words
    float* part  = (float*)(hs + 2 * 8 * HW);    // [NW][8][20]

    const int tid = threadIdx.x, lane = tid & 31, warp = tid >> 5;
    const int g = lane >> 2, tg = lane & 3;
    const uint32_t rank = my_ctarank();
    const int bg = blockIdx.x >> 3;
    const int jbase = (int)rank * JPC;
    const int bglob0 = bg * 8;

    const uint32_t mbb = smem_u32(smem_u);
    const uint32_t FULL0 = mbb, FULL1 = mbb + 8u, EMPT0 = mbb + 16u, EMPT1 = mbb + 24u;

    // ---- preload packed fp16 weight fragments (once) ----
    unsigned areg[KS][4];
    {
        int lr0 = warp * 16 + g, lr1 = lr0 + 8;
        const float* w0 = Whh + (size_t)((lr0 & 3) * HD + jbase + (lr0 >> 2)) * HD;
        const float* w1 = Whh + (size_t)((lr1 & 3) * HD + jbase + (lr1 >> 2)) * HD;
#pragma unroll
        for (int ks = 0; ks < KS; ks++) {
            __half2 p0 = __floats2half2_rn(w0[ks * 16 + tg * 2],     w0[ks * 16 + tg * 2 + 1]);
            __half2 p1 = __floats2half2_rn(w1[ks * 16 + tg * 2],     w1[ks * 16 + tg * 2 + 1]);
            __half2 p2 = __floats2half2_rn(w0[ks * 16 + 8 + tg * 2], w0[ks * 16 + 8 + tg * 2 + 1]);
            __half2 p3 = __floats2half2_rn(w1[ks * 16 + 8 + tg * 2], w1[ks * 16 + 8 + tg * 2 + 1]);
            areg[ks][0] = *(unsigned*)&p0;
            areg[ks][1] = *(unsigned*)&p1;
            areg[ks][2] = *(unsigned*)&p2;
            areg[ks][3] = *(unsigned*)&p3;
        }
    }

    for (int i = tid; i < 2 * 8 * HW; i += NT) hs[i] = 0u;
    if (tid == 0) {
        mbar_init(FULL0, 1); mbar_init(FULL1, 1);
        mbar_init(EMPT0, ECNT); mbar_init(EMPT1, ECNT);
        mbar_expect_tx(FULL1, FBYTES);
    }
    __syncthreads();
    CLUSTER_ARRIVE();
    CLUSTER_WAIT();

    // updater mapping: lane -> (batch = lane&7, local unit = lane>>3)
    const int b  = lane & 7;
    const int ul = lane >> 3;
    const int j  = jbase + warp * 4 + ul;
    const float* xgp = xg + ((size_t)(bglob0 + b) * T) * (4 * HD) + j * 4;
    float* pw = part + warp * 160;
    const uint32_t hs_base = smem_u32(hs);
    float cc = 0.f;
    float4 xv = *(const float4*)xgp;
    unsigned phf0 = 0, phf1 = 0, phe0 = 0, phe1 = 0;

    for (int t = 0; t < T; t++) {
        const int rb = t & 1, wb = rb ^ 1;

        if (t > 0) {
            if (rb) { mbar_wait(FULL1, phf1); phf1 ^= 1; }
            else    { mbar_wait(FULL0, phf0); phf0 ^= 1; }
        }
        if (tid == 0) mbar_expect_tx(rb ? FULL1 : FULL0, FBYTES);

        // ---- mma: rows [warp*16,+16) x 8 batches, k = HD ----
        float s0, s1, s2, s3;
        {
            float acc[4][4];
#pragma unroll
            for (int ch = 0; ch < 4; ch++)
#pragma unroll
                for (int i = 0; i < 4; i++) acc[ch][i] = 0.f;

            const unsigned* hb = hs + rb * 8 * HW + g * HW;   // batch g
#pragma unroll
            for (int ks = 0; ks < KS; ks++) {
                unsigned bf[2];
                bf[0] = hb[ks * 8 + tg];
                bf[1] = hb[ks * 8 + tg + 4];
                mma_f16(acc[ks & 3], areg[ks], bf);
            }
            s0 = (acc[0][0] + acc[1][0]) + (acc[2][0] + acc[3][0]);
            s1 = (acc[0][1] + acc[1][1]) + (acc[2][1] + acc[3][1]);
            s2 = (acc[0][2] + acc[1][2]) + (acc[2][2] + acc[3][2]);
            s3 = (acc[0][3] + acc[1][3]) + (acc[2][3] + acc[3][3]);
        }

        // this warp is done reading hs[rb]: release read-lock to all CTAs
        if (lane == 0) {
            uint32_t eb = rb ? EMPT1 : EMPT0;
#pragma unroll
            for (int r = 0; r < 8; r++) mbar_arrive_remote(eb, r);
        }

        // ---- warp-local gate transpose through smem patch ----
        // write: [col=batch][row=gate-row] (stride 20, conflict-free)
        pw[(2 * tg) * 20 + g]         = s0;
        pw[(2 * tg + 1) * 20 + g]     = s1;
        pw[(2 * tg) * 20 + g + 8]     = s2;
        pw[(2 * tg + 1) * 20 + g + 8] = s3;
        __syncwarp();
        float4 p = *(const float4*)(pw + b * 20 + 4 * ul);  // (i,f,c,o) of (b, ul)

        float iv = fsigmoid(p.x + xv.x);
        float fv = fsigmoid(p.y + xv.y);
        float gv = ftanh(p.z + xv.z);
        float ov = fsigmoid(p.w + xv.w);
        cc = fv * cc + iv * gv;
        float hval = ov * ftanh(cc);

        // pair with neighbor unit (ul^1) for half2 packing
        float nbh = __shfl_xor_sync(0xffffffffu, hval, 8);

        if (t > 0) {
            if (wb) { mbar_wait(EMPT1, phe1); phe1 ^= 1; }
            else    { mbar_wait(EMPT0, phe0); phe0 ^= 1; }
        }

        if ((ul & 1) == 0) {
            __half2 h2 = __floats2half2_rn(hval, nbh);    // low = even unit
            unsigned hbits = *(unsigned*)&h2;
            uint32_t loff = hs_base +
                4u * (uint32_t)((wb * 8 + b) * HW + (j >> 1));
            uint32_t fb = wb ? FULL1 : FULL0;
#pragma unroll
            for (int r = 0; r < 8; r++) st_async_b32(loff, hbits, fb, r);
            if (STORE_OUT)
                *(__half2*)(out + ((size_t)(bglob0 + b) * T + t) * HD + j) = h2;
        }
        if (hfin && t == T - 1)
            hfin[(size_t)(bglob0 + b) * HD + j] = hval;

        if (t + 1 < T)
            xv = *(const float4*)(xgp + (size_t)(t + 1) * (4 * HD));
    }

    mbar_wait(FULL0, phf0);
    CLUSTER_ARRIVE();
    CLUSTER_WAIT();
}

// ---------------- FC head (parallel): 64 blocks x 64 threads ----------------
__global__ void __launch_bounds__(64) fc_head_par(
    const float* __restrict__ h2,     // [64][128]
    const float* __restrict__ Wfc,    // [64][128]
    const float* __restrict__ bfc,    // [64]
    const float* __restrict__ Wout,   // [1][64]
    const float* __restrict__ bout,   // [1]
    float* __restrict__ outp)         // [64]
{
    __shared__ float hrs[128];
    __shared__ float red[64];
    const int b = blockIdx.x, u = threadIdx.x;

    ((float2*)hrs)[u] = ((const float2*)(h2 + b * 128))[u];
    __syncthreads();

    const float4* wr = (const float4*)(Wfc + u * 128);
    float s0 = 0.f, s1 = 0.f, s2 = 0.f, s3 = 0.f;
#pragma unroll
    for (int k = 0; k < 32; k += 4) {
        float4 w0 = wr[k],     w1 = wr[k + 1], w2 = wr[k + 2], w3 = wr[k + 3];
        const float* h0 = hrs + k * 4;
        s0 += w0.x * h0[0]  + w0.y * h0[1]  + w0.z * h0[2]  + w0.w * h0[3];
        s1 += w1.x * h0[4]  + w1.y * h0[5]  + w1.z * h0[6]  + w1.w * h0[7];
        s2 += w2.x * h0[8]  + w2.y * h0[9]  + w2.z * h0[10] + w2.w * h0[11];
        s3 += w3.x * h0[12] + w3.y * h0[13] + w3.z * h0[14] + w3.w * h0[15];
    }
    float s = (s0 + s1) + (s2 + s3) + bfc[u];
    red[u] = fmaxf(s, 0.f) * Wout[u];
    __syncthreads();

    if (u < 32) {
        float v = red[u] + red[u + 32];
#pragma unroll
        for (int off = 16; off > 0; off >>= 1)
            v += __shfl_down_sync(0xffffffffu, v, off);
        if (u == 0) outp[b] = v + bout[0];
    }
}

// ---------------- launch ----------------
extern "C" void kernel_launch(void* const* d_in, const int* in_sizes, int n_in,
                              void* d_out, int out_size)
{
    const float* x    = (const float*)d_in[0];
    const float* Wih1 = (const float*)d_in[1];
    const float* Whh1 = (const float*)d_in[2];
    const float* bih1 = (const float*)d_in[3];
    const float* bhh1 = (const float*)d_in[4];
    const float* Wih2 = (const float*)d_in[5];
    const float* Whh2 = (const float*)d_in[6];
    const float* bih2 = (const float*)d_in[7];
    const float* bhh2 = (const float*)d_in[8];
    const float* Wfc1 = (const float*)d_in[9];
    const float* bfc1 = (const float*)d_in[10];
    const float* Wout = (const float*)d_in[11];
    const float* bout = (const float*)d_in[12];
    float* outp = (float*)d_out;

    __half *xh, *out1h, *w1h, *w2h;
    float *xg1, *xg2, *h2f;
    cudaGetSymbolAddress((void**)&xh,    g_xh);
    cudaGetSymbolAddress((void**)&xg1,   g_xg1);
    cudaGetSymbolAddress((void**)&out1h, g_out1);
    cudaGetSymbolAddress((void**)&xg2,   g_xg2);
    cudaGetSymbolAddress((void**)&w1h,   g_w1h);
    cudaGetSymbolAddress((void**)&w2h,   g_w2h);
    cudaGetSymbolAddress((void**)&h2f,   g_h2f);

    const int GEMM_SMEM = 2 * 128 * 36 * 4 * 2;                       // 73728 B
    const int R1_SMEM = 32 + (2 * 8 * 132) * 4 + 8 * 160 * 4;         // 13600 B
    const int R2_SMEM = 32 + (2 * 8 * 68) * 4 + 4 * 160 * 4;          // 6944 B
    cudaFuncSetAttribute(gemm_f16_perm,
                         cudaFuncAttributeMaxDynamicSharedMemorySize, GEMM_SMEM);
    cudaFuncSetAttribute(lstm_recur_w<256, 32, 256, true>,
                         cudaFuncAttributeMaxDynamicSharedMemorySize, 64 * 1024);
    cudaFuncSetAttribute(lstm_recur_w<128, 16, 128, false>,
                         cudaFuncAttributeMaxDynamicSharedMemorySize, 64 * 1024);

    // prep: fp16 conversions
    cvt_f16_kernel<<<(32768 * 2048 / 4 + 255) / 256, 256>>>(x, xh, 32768 * 2048);
    cvt_f16_kernel<<<(1024 * 2048 / 4 + 255) / 256, 256>>>(Wih1, w1h, 1024 * 2048);
    cvt_f16_kernel<<<(512 * 256 / 4 + 255) / 256, 256>>>(Wih2, w2h, 512 * 256);

    const int M = 64 * 512;

    // layer 1 input projection (fp16 mma, LDSM)
    gemm_f16_perm<<<dim3(1024 / 128, M / 128), 256, GEMM_SMEM>>>(
        xh, w1h, bih1, bhh1, xg1, M, 1024, 2048);

    // layer 1 recurrence
    lstm_recur_w<256, 32, 256, true><<<64, 256, R1_SMEM>>>(
        xg1, Whh1, out1h, (float*)0, 512);

    // layer 2 input projection
    gemm_f16_perm<<<dim3(512 / 128, M / 128), 256, GEMM_SMEM>>>(
        out1h, w2h, bih2, bhh2, xg2, M, 512, 256);

    // layer 2 recurrence
    lstm_recur_w<128, 16, 128, false><<<64, 128, R2_SMEM>>>(
        xg2, Whh2, (__half*)0, h2f, 512);

    // FC head (parallel)
    fc_head_par<<<64, 64>>>(h2f, Wfc1, bfc1, Wout, bout, outp);
}

// round 13
// speedup vs baseline: 1.1345x; 1.1345x over previous
#include <cuda_runtime.h>
#include <cuda_fp16.h>
#include <math.h>
#include <stdint.h>

// ---------------- static device scratch (no allocation allowed) ----------------
__device__ __half  g_xh  [(size_t)32768 * 2048];   // x converted to fp16
__device__ float   g_xg1 [(size_t)32768 * 1024];   // layer1 gates [b][t][j*4+g] (fp32)
__device__ __half  g_out1[(size_t)32768 * 256];    // layer1 hidden outputs (fp16)
__device__ float   g_xg2 [(size_t)32768 * 512];    // layer2 gates [b][t][j*4+g] (fp32)
__device__ __half  g_w1h [(size_t)1024 * 2048];    // Wih1 fp16
__device__ __half  g_w2h [(size_t)512 * 256];      // Wih2 fp16
__device__ float   g_h2f [64 * 128];               // final layer2 h (fp32)

// ---------------- helpers ----------------
__device__ __forceinline__ void mma_f16(float* c, const unsigned* a, const unsigned* b) {
    asm volatile(
        "mma.sync.aligned.m16n8k16.row.col.f32.f16.f16.f32 "
        "{%0,%1,%2,%3},{%4,%5,%6,%7},{%8,%9},{%0,%1,%2,%3};"
        : "+f"(c[0]), "+f"(c[1]), "+f"(c[2]), "+f"(c[3])
        : "r"(a[0]), "r"(a[1]), "r"(a[2]), "r"(a[3]), "r"(b[0]), "r"(b[1]));
}

__device__ __forceinline__ void cp_async16(void* smem_dst, const void* gptr) {
    unsigned s = (unsigned)__cvta_generic_to_shared(smem_dst);
    asm volatile("cp.async.cg.shared.global [%0], [%1], 16;\n" :: "r"(s), "l"(gptr));
}
#define CP_COMMIT() asm volatile("cp.async.commit_group;\n" ::: "memory")
#define CP_WAIT0()  asm volatile("cp.async.wait_group 0;\n" ::: "memory")

__device__ __forceinline__ uint32_t smem_u32(const void* p) {
    return (uint32_t)__cvta_generic_to_shared(p);
}
__device__ __forceinline__ uint32_t my_ctarank() {
    uint32_t r;
    asm("mov.u32 %0, %%cluster_ctarank;" : "=r"(r));
    return r;
}
#define CLUSTER_ARRIVE() asm volatile("barrier.cluster.arrive.aligned;" ::: "memory")
#define CLUSTER_WAIT()   asm volatile("barrier.cluster.wait.aligned;" ::: "memory")

__device__ __forceinline__ void mbar_init(uint32_t a, unsigned cnt) {
    asm volatile("mbarrier.init.shared.b64 [%0], %1;" :: "r"(a), "r"(cnt) : "memory");
}
__device__ __forceinline__ void mbar_expect_tx(uint32_t a, unsigned tx) {
    asm volatile("mbarrier.arrive.expect_tx.shared.b64 _, [%0], %1;"
                 :: "r"(a), "r"(tx) : "memory");
}
__device__ __forceinline__ void mbar_wait(uint32_t a, unsigned parity) {
    asm volatile(
        "{\n\t"
        ".reg .pred P1;\n\t"
        "WAIT_LOOP_%=:\n\t"
        "mbarrier.try_wait.parity.acquire.cta.shared::cta.b64 P1, [%0], %1, 0x989680;\n\t"
        "@P1 bra.uni WAIT_DONE_%=;\n\t"
        "bra.uni WAIT_LOOP_%=;\n\t"
        "WAIT_DONE_%=:\n\t"
        "}"
        :: "r"(a), "r"(parity) : "memory");
}
__device__ __forceinline__ void mbar_arrive_remote(uint32_t local_addr, int rank) {
    uint32_t ra;
    asm("mapa.shared::cluster.u32 %0, %1, %2;" : "=r"(ra) : "r"(local_addr), "r"(rank));
    asm volatile("mbarrier.arrive.shared::cluster.b64 _, [%0];" :: "r"(ra) : "memory");
}
__device__ __forceinline__ void st_async_b32(uint32_t local_dst, unsigned val,
                                             uint32_t local_mbar, int rank) {
    uint32_t ra, rm;
    asm("mapa.shared::cluster.u32 %0, %1, %2;" : "=r"(ra) : "r"(local_dst), "r"(rank));
    asm("mapa.shared::cluster.u32 %0, %1, %2;" : "=r"(rm) : "r"(local_mbar), "r"(rank));
    asm volatile("st.async.shared::cluster.mbarrier::complete_tx::bytes.b32 [%0], %1, [%2];"
                 :: "r"(ra), "r"(val), "r"(rm) : "memory");
}

// fast precise activations (MUFU ex2 + rcp; err ~1e-6)
__device__ __forceinline__ float fsigmoid(float x) {
    return 1.f / (1.f + __expf(-x));
}
__device__ __forceinline__ float ftanh(float x) {
    return 1.f - 2.f / (1.f + __expf(2.f * x));
}

// ---------------- prep: convert fp32 -> fp16 ----------------
__global__ void cvt_f16_kernel(const float* __restrict__ src, __half* __restrict__ dst, int n) {
    int i = (blockIdx.x * 256 + threadIdx.x) * 4;
    if (i < n) {
        float4 v = *(const float4*)(src + i);
        *(__half2*)(dst + i)     = __floats2half2_rn(v.x, v.y);
        *(__half2*)(dst + i + 2) = __floats2half2_rn(v.z, v.w);
    }
}

// ---------------- fp16 GEMM with permuted output columns (Round-11 version) ----------------
// C[m][n'] = sum_k A[m][k]*W[srcrow(n')][k] + b1[srcrow]+b2[srcrow], n'=j*4+g -> g*H+j.
// Tiles: 128M x 128N x 64K, 256 threads, 8 warps (2m x 4n, warp tile 64x32),
// double-buffered cp.async, m16n8k16 fp16 mma (fp32 accum), scalar LDS fragments.
__global__ void __launch_bounds__(256, 2) gemm_f16_perm(
    const __half* __restrict__ A, const __half* __restrict__ W,
    const float* __restrict__ b1, const float* __restrict__ b2,
    float* __restrict__ C, int M, int N, int K)
{
    extern __shared__ unsigned sh[];
    unsigned* As = sh;                 // [2][128][36] (words of half2, 32 used)
    unsigned* Bs = sh + 2 * 128 * 36;  // [2][128][36]

    const int tid = threadIdx.x, lane = tid & 31, warp = tid >> 5;
    const int wm = warp & 1, wn = warp >> 1;
    const int g = lane >> 2, tg = lane & 3;
    const int bn = blockIdx.x * 128, bm = blockIdx.y * 128;
    const int H = N >> 2;

    float acc[4][4][4];
#pragma unroll
    for (int a = 0; a < 4; a++)
#pragma unroll
        for (int b = 0; b < 4; b++)
#pragma unroll
            for (int c = 0; c < 4; c++) acc[a][b][c] = 0.f;

    const int NK = K >> 6;    // 64 k per tile

    // prologue: tile 0 (A/B each: 128 rows x 8 float4)
#pragma unroll
    for (int i = 0; i < 4; i++) {
        int id = tid + i * 256, row = id >> 3, c4 = id & 7;
        cp_async16(&As[row * 36 + c4 * 4], A + (size_t)(bm + row) * K + c4 * 8);
        int np = bn + row;
        int srow = (np & 3) * H + (np >> 2);
        cp_async16(&Bs[row * 36 + c4 * 4], W + (size_t)srow * K + c4 * 8);
    }
    CP_COMMIT();

    int buf = 0;
    for (int kt = 0; kt < NK; kt++) {
        CP_WAIT0();
        __syncthreads();
        if (kt + 1 < NK) {
            int koff = (kt + 1) * 64;
            int nb = buf ^ 1;
#pragma unroll
            for (int i = 0; i < 4; i++) {
                int id = tid + i * 256, row = id >> 3, c4 = id & 7;
                cp_async16(&As[nb * 128 * 36 + row * 36 + c4 * 4],
                           A + (size_t)(bm + row) * K + koff + c4 * 8);
                int np = bn + row;
                int srow = (np & 3) * H + (np >> 2);
                cp_async16(&Bs[nb * 128 * 36 + row * 36 + c4 * 4],
                           W + (size_t)srow * K + koff + c4 * 8);
            }
        }
        CP_COMMIT();

        const unsigned* Ab = As + buf * 128 * 36;
        const unsigned* Bb = Bs + buf * 128 * 36;
#pragma unroll
        for (int ks = 0; ks < 4; ks++) {   // 4 x k=16 slices
            unsigned af[4][4], bf[4][2];
#pragma unroll
            for (int mt = 0; mt < 4; mt++) {
                int r = wm * 64 + mt * 16 + g;
                af[mt][0] = Ab[r * 36 + ks * 8 + tg];
                af[mt][1] = Ab[(r + 8) * 36 + ks * 8 + tg];
                af[mt][2] = Ab[r * 36 + ks * 8 + tg + 4];
                af[mt][3] = Ab[(r + 8) * 36 + ks * 8 + tg + 4];
            }
#pragma unroll
            for (int nt = 0; nt < 4; nt++) {
                int nl = wn * 32 + nt * 8 + g;
                bf[nt][0] = Bb[nl * 36 + ks * 8 + tg];
                bf[nt][1] = Bb[nl * 36 + ks * 8 + tg + 4];
            }
#pragma unroll
            for (int mt = 0; mt < 4; mt++)
#pragma unroll
                for (int nt = 0; nt < 4; nt++)
                    mma_f16(acc[mt][nt], af[mt], bf[nt]);
        }
        buf ^= 1;
    }

    // epilogue: permuted bias + fp32 store
#pragma unroll
    for (int mt = 0; mt < 4; mt++) {
        int r0 = bm + wm * 64 + mt * 16 + g;
#pragma unroll
        for (int nt = 0; nt < 4; nt++) {
            int c = bn + wn * 32 + nt * 8 + tg * 2;
            int s0 = (c & 3) * H + (c >> 2);
            int s1 = ((c + 1) & 3) * H + ((c + 1) >> 2);
            float bb0 = b1[s0] + b2[s0];
            float bb1 = b1[s1] + b2[s1];
            C[(size_t)r0 * N + c]           = acc[mt][nt][0] + bb0;
            C[(size_t)r0 * N + c + 1]       = acc[mt][nt][1] + bb1;
            C[(size_t)(r0 + 8) * N + c]     = acc[mt][nt][2] + bb0;
            C[(size_t)(r0 + 8) * N + c + 1] = acc[mt][nt][3] + bb1;
        }
    }
}

// ---------------- cluster LSTM recurrence, fp16 MMA + st.async/mbarrier ----------------
// Round-11 structure; changes: 8 independent accumulator chains (dependency
// depth 2), expect_tx re-arm hoisted to right after the FULL wait.
template <int HD, int JPC, int NT, bool STORE_OUT>
__global__ void __launch_bounds__(NT, 1) __cluster_dims__(8, 1, 1)
lstm_recur_f16(const float* __restrict__ xg,    // [b][t][j*4+g] fp32
               const float* __restrict__ Whh,   // [4*HD][HD] fp32
               __half* __restrict__ out,        // [b][t][HD] fp16 (layer1) or null
               float* __restrict__ hfin,        // [64][HD] fp32 (layer2) or null
               int T)
{
    constexpr int KS = HD / 16;            // mma k-steps
    constexpr int HW = HD / 2 + 4;         // padded half2-words per batch row
    constexpr int RP = 4 * JPC + 4;        // padded partial row stride
    constexpr int NCH = (KS < 8) ? KS : 8; // accumulator chains
    constexpr unsigned FBYTES = 16u * HD;  // 8 batches * HD * 2 B per phase

    extern __shared__ unsigned smem_u[];
    unsigned* hs = smem_u + 8;                   // [2][8][HW] half2 words
    float* part  = (float*)(hs + 2 * 8 * HW);    // [8][RP]

    const int tid = threadIdx.x, lane = tid & 31, warp = tid >> 5;
    const int g = lane >> 2, tg = lane & 3;
    const uint32_t rank = my_ctarank();
    const int bg = blockIdx.x >> 3;
    const int jbase = (int)rank * JPC;
    const int bglob0 = bg * 8;

    const uint32_t mbb = smem_u32(smem_u);
    const uint32_t FULL0 = mbb, FULL1 = mbb + 8u, EMPT0 = mbb + 16u, EMPT1 = mbb + 24u;

    // ---- preload packed fp16 weight fragments (once) ----
    unsigned areg[KS][4];
    {
        int lr0 = warp * 16 + g, lr1 = lr0 + 8;
        const float* w0 = Whh + (size_t)((lr0 & 3) * HD + jbase + (lr0 >> 2)) * HD;
        const float* w1 = Whh + (size_t)((lr1 & 3) * HD + jbase + (lr1 >> 2)) * HD;
#pragma unroll
        for (int ks = 0; ks < KS; ks++) {
            __half2 p0 = __floats2half2_rn(w0[ks * 16 + tg * 2],     w0[ks * 16 + tg * 2 + 1]);
            __half2 p1 = __floats2half2_rn(w1[ks * 16 + tg * 2],     w1[ks * 16 + tg * 2 + 1]);
            __half2 p2 = __floats2half2_rn(w0[ks * 16 + 8 + tg * 2], w0[ks * 16 + 8 + tg * 2 + 1]);
            __half2 p3 = __floats2half2_rn(w1[ks * 16 + 8 + tg * 2], w1[ks * 16 + 8 + tg * 2 + 1]);
            areg[ks][0] = *(unsigned*)&p0;
            areg[ks][1] = *(unsigned*)&p1;
            areg[ks][2] = *(unsigned*)&p2;
            areg[ks][3] = *(unsigned*)&p3;
        }
    }

    for (int i = tid; i < 2 * 8 * HW; i += NT) hs[i] = 0u;
    if (tid == 0) {
        mbar_init(FULL0, 1); mbar_init(FULL1, 1);
        mbar_init(EMPT0, 8); mbar_init(EMPT1, 8);
        mbar_expect_tx(FULL1, FBYTES);
    }
    __syncthreads();
    CLUSTER_ARRIVE();
    CLUSTER_WAIT();

    const int b  = tid / JPC;
    const int jl = tid % JPC;
    const float* xgp = xg + ((size_t)(bglob0 + b) * T) * (4 * HD) + (jbase + jl) * 4;
    const uint32_t hs_base = smem_u32(hs);
    float cc = 0.f;
    float4 xv = *(const float4*)xgp;
    unsigned phf0 = 0, phf1 = 0, phe0 = 0, phe1 = 0;

    for (int t = 0; t < T; t++) {
        const int rb = t & 1, wb = rb ^ 1;

        if (t > 0) {
            if (rb) { mbar_wait(FULL1, phf1); phf1 ^= 1; }
            else    { mbar_wait(FULL0, phf0); phf0 ^= 1; }
        }
        // re-arm FULL[rb] for its next phase now (writers still gated by EMPT[rb])
        if (tid == 0) mbar_expect_tx(rb ? FULL1 : FULL0, FBYTES);

        // ---- mma: rows [warp*16,+16) x 8 batches, k = HD, NCH chains ----
        {
            float acc[NCH][4];
#pragma unroll
            for (int ch = 0; ch < NCH; ch++)
#pragma unroll
                for (int i = 0; i < 4; i++) acc[ch][i] = 0.f;

            const unsigned* hb = hs + rb * 8 * HW + g * HW;   // batch g
#pragma unroll
            for (int ks = 0; ks < KS; ks++) {
                unsigned bf[2];
                bf[0] = hb[ks * 8 + tg];
                bf[1] = hb[ks * 8 + tg + 4];
                mma_f16(acc[ks % NCH], areg[ks], bf);
            }
            float r0 = 0.f, r1 = 0.f, r2 = 0.f, r3 = 0.f;
#pragma unroll
            for (int ch = 0; ch < NCH; ch++) {
                r0 += acc[ch][0]; r1 += acc[ch][1];
                r2 += acc[ch][2]; r3 += acc[ch][3];
            }
            int lr = warp * 16 + g;
            part[(tg * 2 + 0) * RP + lr]     = r0;
            part[(tg * 2 + 1) * RP + lr]     = r1;
            part[(tg * 2 + 0) * RP + lr + 8] = r2;
            part[(tg * 2 + 1) * RP + lr + 8] = r3;
        }
        __syncthreads();

        if (tid == 0) {
            uint32_t eb = rb ? EMPT1 : EMPT0;
#pragma unroll
            for (int r = 0; r < 8; r++) mbar_arrive_remote(eb, r);
        }

        // ---- update one (batch, unit) ----
        float4 p = *(const float4*)(part + b * RP + jl * 4);
        float iv = fsigmoid(p.x + xv.x);
        float fv = fsigmoid(p.y + xv.y);
        float gv = ftanh(p.z + xv.z);
        float ov = fsigmoid(p.w + xv.w);
        cc = fv * cc + iv * gv;
        float hval = ov * ftanh(cc);

        // pair with neighbor unit (jl^1 is the adjacent lane)
        float nbh = __shfl_xor_sync(0xffffffffu, hval, 1);

        if (t > 0) {
            if (wb) { mbar_wait(EMPT1, phe1); phe1 ^= 1; }
            else    { mbar_wait(EMPT0, phe0); phe0 ^= 1; }
        }

        if ((jl & 1) == 0) {
            __half2 h2 = __floats2half2_rn(hval, nbh);    // low = even unit
            unsigned hbits = *(unsigned*)&h2;
            uint32_t loff = hs_base +
                4u * (uint32_t)((wb * 8 + b) * HW + ((jbase + jl) >> 1));
            uint32_t fb = wb ? FULL1 : FULL0;
#pragma unroll
            for (int r = 0; r < 8; r++) st_async_b32(loff, hbits, fb, r);
            if (STORE_OUT)
                *(__half2*)(out + ((size_t)(bglob0 + b) * T + t) * HD + jbase + jl) = h2;
        }
        if (hfin && t == T - 1)
            hfin[(size_t)(bglob0 + b) * HD + jbase + jl] = hval;

        if (t + 1 < T)
            xv = *(const float4*)(xgp + (size_t)(t + 1) * (4 * HD));
    }

    mbar_wait(FULL0, phf0);
    CLUSTER_ARRIVE();
    CLUSTER_WAIT();
}

// ---------------- FC head (parallel): 64 blocks x 64 threads ----------------
__global__ void __launch_bounds__(64) fc_head_par(
    const float* __restrict__ h2,     // [64][128]
    const float* __restrict__ Wfc,    // [64][128]
    const float* __restrict__ bfc,    // [64]
    const float* __restrict__ Wout,   // [1][64]
    const float* __restrict__ bout,   // [1]
    float* __restrict__ outp)         // [64]
{
    __shared__ float hrs[128];
    __shared__ float red[64];
    const int b = blockIdx.x, u = threadIdx.x;

    ((float2*)hrs)[u] = ((const float2*)(h2 + b * 128))[u];
    __syncthreads();

    const float4* wr = (const float4*)(Wfc + u * 128);
    float s0 = 0.f, s1 = 0.f, s2 = 0.f, s3 = 0.f;
#pragma unroll
    for (int k = 0; k < 32; k += 4) {
        float4 w0 = wr[k],     w1 = wr[k + 1], w2 = wr[k + 2], w3 = wr[k + 3];
        const float* h0 = hrs + k * 4;
        s0 += w0.x * h0[0]  + w0.y * h0[1]  + w0.z * h0[2]  + w0.w * h0[3];
        s1 += w1.x * h0[4]  + w1.y * h0[5]  + w1.z * h0[6]  + w1.w * h0[7];
        s2 += w2.x * h0[8]  + w2.y * h0[9]  + w2.z * h0[10] + w2.w * h0[11];
        s3 += w3.x * h0[12] + w3.y * h0[13] + w3.z * h0[14] + w3.w * h0[15];
    }
    float s = (s0 + s1) + (s2 + s3) + bfc[u];
    red[u] = fmaxf(s, 0.f) * Wout[u];
    __syncthreads();

    if (u < 32) {
        float v = red[u] + red[u + 32];
#pragma unroll
        for (int off = 16; off > 0; off >>= 1)
            v += __shfl_down_sync(0xffffffffu, v, off);
        if (u == 0) outp[b] = v + bout[0];
    }
}

// ---------------- launch ----------------
extern "C" void kernel_launch(void* const* d_in, const int* in_sizes, int n_in,
                              void* d_out, int out_size)
{
    const float* x    = (const float*)d_in[0];
    const float* Wih1 = (const float*)d_in[1];
    const float* Whh1 = (const float*)d_in[2];
    const float* bih1 = (const float*)d_in[3];
    const float* bhh1 = (const float*)d_in[4];
    const float* Wih2 = (const float*)d_in[5];
    const float* Whh2 = (const float*)d_in[6];
    const float* bih2 = (const float*)d_in[7];
    const float* bhh2 = (const float*)d_in[8];
    const float* Wfc1 = (const float*)d_in[9];
    const float* bfc1 = (const float*)d_in[10];
    const float* Wout = (const float*)d_in[11];
    const float* bout = (const float*)d_in[12];
    float* outp = (float*)d_out;

    __half *xh, *out1h, *w1h, *w2h;
    float *xg1, *xg2, *h2f;
    cudaGetSymbolAddress((void**)&xh,    g_xh);
    cudaGetSymbolAddress((void**)&xg1,   g_xg1);
    cudaGetSymbolAddress((void**)&out1h, g_out1);
    cudaGetSymbolAddress((void**)&xg2,   g_xg2);
    cudaGetSymbolAddress((void**)&w1h,   g_w1h);
    cudaGetSymbolAddress((void**)&w2h,   g_w2h);
    cudaGetSymbolAddress((void**)&h2f,   g_h2f);

    const int GEMM_SMEM = 2 * 128 * 36 * 4 * 2;                    // 73728 B
    const int R1_SMEM = 32 + (2 * 8 * 132) * 4 + 8 * 132 * 4;      // 12704 B
    const int R2_SMEM = 32 + (2 * 8 * 68) * 4 + 8 * 68 * 4;        // 6560 B
    cudaFuncSetAttribute(gemm_f16_perm,
                         cudaFuncAttributeMaxDynamicSharedMemorySize, GEMM_SMEM);
    cudaFuncSetAttribute(lstm_recur_f16<256, 32, 256, true>,
                         cudaFuncAttributeMaxDynamicSharedMemorySize, 64 * 1024);
    cudaFuncSetAttribute(lstm_recur_f16<128, 16, 128, false>,
                         cudaFuncAttributeMaxDynamicSharedMemorySize, 64 * 1024);

    // prep: fp16 conversions
    cvt_f16_kernel<<<(32768 * 2048 / 4 + 255) / 256, 256>>>(x, xh, 32768 * 2048);
    cvt_f16_kernel<<<(1024 * 2048 / 4 + 255) / 256, 256>>>(Wih1, w1h, 1024 * 2048);
    cvt_f16_kernel<<<(512 * 256 / 4 + 255) / 256, 256>>>(Wih2, w2h, 512 * 256);

    const int M = 64 * 512;

    // layer 1 input projection (fp16 mma)
    gemm_f16_perm<<<dim3(1024 / 128, M / 128), 256, GEMM_SMEM>>>(
        xh, w1h, bih1, bhh1, xg1, M, 1024, 2048);

    // layer 1 recurrence
    lstm_recur_f16<256, 32, 256, true><<<64, 256, R1_SMEM>>>(
        xg1, Whh1, out1h, (float*)0, 512);

    // layer 2 input projection (A = fp16 out1)
    gemm_f16_perm<<<dim3(512 / 128, M / 128), 256, GEMM_SMEM>>>(
        out1h, w2h, bih2, bhh2, xg2, M, 512, 256);

    // layer 2 recurrence
    lstm_recur_f16<128, 16, 128, false><<<64, 128, R2_SMEM>>>(
        xg2, Whh2, (__half*)0, h2f, 512);

    // FC head (parallel)
    fc_head_par<<<64, 64>>>(h2f, Wfc1, bfc1, Wout, bout, outp);
}